// round 8
// baseline (speedup 1.0000x reference)
#include <cuda_runtime.h>
#include <math.h>

static constexpr int D     = 512;     // feature dim (float32)
static constexpr int BLOCK = 256;     // 8 warps per block, 1 warp per edge
#define MAX_BLOCKS 32768              // 200k edges / 8 warps = 25000 blocks

__device__ float        g_partials[MAX_BLOCKS];
__device__ unsigned int g_done;       // zero at module load; self-resets per launch

__device__ __forceinline__ float ldcg(const float* p) {
    float v;
    asm volatile("ld.global.cg.f32 %0, [%1];" : "=f"(v) : "l"(p));
    return v;
}

// One warp per edge (max MLP per warp, fast block turnover keeps the L1tex
// queue full). Block partials -> g_partials; the LAST block to arrive at the
// done-counter reduces all partials and writes the mean (fixed order ->
// deterministic). No second kernel launch.
__global__ void __launch_bounds__(BLOCK) edge_loss_kernel(
    const float* __restrict__ feat,
    const int*   __restrict__ pos_src,
    const int*   __restrict__ pos_dst,
    const int*   __restrict__ neg_src,
    const int*   __restrict__ neg_dst,
    int e_pos, int e_total, int n_blocks, float inv_total,
    float* __restrict__ out)
{
    const int lane = threadIdx.x & 31;
    const int wid  = threadIdx.x >> 5;
    const int warp_global = (blockIdx.x * BLOCK + threadIdx.x) >> 5;

    float term = 0.0f;

    if (warp_global < e_total) {
        int s, d;
        const bool is_pos = (warp_global < e_pos);
        if (is_pos) {
            s = pos_src[warp_global];
            d = pos_dst[warp_global];
        } else {
            s = neg_src[warp_global - e_pos];
            d = neg_dst[warp_global - e_pos];
        }

        const float4* __restrict__ u =
            reinterpret_cast<const float4*>(feat + (size_t)s * D);
        const float4* __restrict__ v =
            reinterpret_cast<const float4*>(feat + (size_t)d * D);

        // 512 floats = 128 float4 per row; lane takes 4 at stride 32.
        // All 8 vector loads issued up front for MLP.
        float4 a0 = u[lane +  0];
        float4 a1 = u[lane + 32];
        float4 a2 = u[lane + 64];
        float4 a3 = u[lane + 96];
        float4 b0 = v[lane +  0];
        float4 b1 = v[lane + 32];
        float4 b2 = v[lane + 64];
        float4 b3 = v[lane + 96];

        float acc = 0.0f;
        acc = fmaf(a0.x, b0.x, acc); acc = fmaf(a0.y, b0.y, acc);
        acc = fmaf(a0.z, b0.z, acc); acc = fmaf(a0.w, b0.w, acc);
        acc = fmaf(a1.x, b1.x, acc); acc = fmaf(a1.y, b1.y, acc);
        acc = fmaf(a1.z, b1.z, acc); acc = fmaf(a1.w, b1.w, acc);
        acc = fmaf(a2.x, b2.x, acc); acc = fmaf(a2.y, b2.y, acc);
        acc = fmaf(a2.z, b2.z, acc); acc = fmaf(a2.w, b2.w, acc);
        acc = fmaf(a3.x, b3.x, acc); acc = fmaf(a3.y, b3.y, acc);
        acc = fmaf(a3.z, b3.z, acc); acc = fmaf(a3.w, b3.w, acc);

        // Warp reduce (deterministic tree).
        #pragma unroll
        for (int off = 16; off > 0; off >>= 1)
            acc += __shfl_xor_sync(0xffffffffu, acc, off);

        const float lab = is_pos ? 1.0f : 0.0f;
        term = fmaxf(acc, 0.0f) - acc * lab + log1pf(expf(-fabsf(acc)));
    }

    // Block reduce in fixed order.
    __shared__ float smem[BLOCK / 32];
    __shared__ bool  is_last;
    if (lane == 0) smem[wid] = term;
    __syncthreads();
    if (threadIdx.x == 0) {
        float sum = 0.0f;
        #pragma unroll
        for (int i = 0; i < BLOCK / 32; i++) sum += smem[i];
        g_partials[blockIdx.x] = sum;
        __threadfence();
        unsigned int old = atomicAdd(&g_done, 1u);
        is_last = (old == (unsigned int)(n_blocks - 1));
    }
    __syncthreads();

    // Last block: reduce all partials. 4 independent accumulators per thread
    // keep ~100 loads pipelined; fixed summation order -> deterministic.
    if (is_last) {
        __shared__ float red[BLOCK];
        float a0 = 0.0f, a1 = 0.0f, a2 = 0.0f, a3 = 0.0f;
        int i = threadIdx.x;
        const int stride = BLOCK;
        for (; i + 3 * stride < n_blocks; i += 4 * stride) {
            a0 += ldcg(&g_partials[i + 0 * stride]);
            a1 += ldcg(&g_partials[i + 1 * stride]);
            a2 += ldcg(&g_partials[i + 2 * stride]);
            a3 += ldcg(&g_partials[i + 3 * stride]);
        }
        for (; i < n_blocks; i += stride)
            a0 += ldcg(&g_partials[i]);
        red[threadIdx.x] = (a0 + a1) + (a2 + a3);
        __syncthreads();
        #pragma unroll
        for (int s = BLOCK / 2; s > 0; s >>= 1) {
            if (threadIdx.x < s) red[threadIdx.x] += red[threadIdx.x + s];
            __syncthreads();
        }
        if (threadIdx.x == 0) {
            *out   = red[0] * inv_total;
            g_done = 0;                       // reset for next graph replay
        }
    }
}

extern "C" void kernel_launch(void* const* d_in, const int* in_sizes, int n_in,
                              void* d_out, int out_size)
{
    const float* feat    = (const float*)d_in[0];
    const int*   pos_src = (const int*)d_in[1];
    const int*   pos_dst = (const int*)d_in[2];
    const int*   neg_src = (const int*)d_in[3];
    const int*   neg_dst = (const int*)d_in[4];
    float* out = (float*)d_out;

    const int e_pos   = in_sizes[1];
    const int e_neg   = in_sizes[3];
    const int e_total = e_pos + e_neg;

    const int warps_per_block = BLOCK / 32;
    int n_blocks = (e_total + warps_per_block - 1) / warps_per_block;
    if (n_blocks > MAX_BLOCKS) n_blocks = MAX_BLOCKS;  // 200k edges -> 25000

    edge_loss_kernel<<<n_blocks, BLOCK>>>(feat, pos_src, pos_dst,
                                          neg_src, neg_dst,
                                          e_pos, e_total, n_blocks,
                                          1.0f / (float)e_total, out);
}

// round 9
// speedup vs baseline: 1.5839x; 1.5839x over previous
#include <cuda_runtime.h>
#include <math.h>

// Scratch for per-block partial sums (no device allocation allowed).
#define MAX_BLOCKS 65536
__device__ float g_partials[MAX_BLOCKS];

static constexpr int D = 512;          // feature dim (float32)
static constexpr int BLOCK = 256;      // 8 warps per block, 1 warp per edge

__device__ __forceinline__ float4 ldcg4(const float4* p) {
    float4 v;
    asm volatile("ld.global.cg.v4.f32 {%0,%1,%2,%3}, [%4];"
                 : "=f"(v.x), "=f"(v.y), "=f"(v.z), "=f"(v.w) : "l"(p));
    return v;
}

// Kernel 1 (UNCHANGED from the proven 53us version): one warp per edge.
// Gather two rows, dot, BCE term, deterministic block reduce into g_partials.
// No fences, no atomics -> short block tail, fast block turnover, L1 intact.
__global__ void __launch_bounds__(BLOCK) edge_loss_kernel(
    const float* __restrict__ feat,
    const int*   __restrict__ pos_src,
    const int*   __restrict__ pos_dst,
    const int*   __restrict__ neg_src,
    const int*   __restrict__ neg_dst,
    int e_pos, int e_total)
{
    const int warp_global = (blockIdx.x * BLOCK + threadIdx.x) >> 5;
    const int lane = threadIdx.x & 31;
    const int wid  = threadIdx.x >> 5;

    float term = 0.0f;

    if (warp_global < e_total) {
        int s, d;
        const bool is_pos = (warp_global < e_pos);
        if (is_pos) {
            s = pos_src[warp_global];
            d = pos_dst[warp_global];
        } else {
            s = neg_src[warp_global - e_pos];
            d = neg_dst[warp_global - e_pos];
        }

        const float4* __restrict__ u =
            reinterpret_cast<const float4*>(feat + (size_t)s * D);
        const float4* __restrict__ v =
            reinterpret_cast<const float4*>(feat + (size_t)d * D);

        // 512 floats = 128 float4 per row; each lane takes 4 at stride 32.
        // All 8 vector loads issued up front for maximum MLP.
        float4 a0 = u[lane +  0];
        float4 a1 = u[lane + 32];
        float4 a2 = u[lane + 64];
        float4 a3 = u[lane + 96];
        float4 b0 = v[lane +  0];
        float4 b1 = v[lane + 32];
        float4 b2 = v[lane + 64];
        float4 b3 = v[lane + 96];

        float acc = 0.0f;
        acc = fmaf(a0.x, b0.x, acc); acc = fmaf(a0.y, b0.y, acc);
        acc = fmaf(a0.z, b0.z, acc); acc = fmaf(a0.w, b0.w, acc);
        acc = fmaf(a1.x, b1.x, acc); acc = fmaf(a1.y, b1.y, acc);
        acc = fmaf(a1.z, b1.z, acc); acc = fmaf(a1.w, b1.w, acc);
        acc = fmaf(a2.x, b2.x, acc); acc = fmaf(a2.y, b2.y, acc);
        acc = fmaf(a2.z, b2.z, acc); acc = fmaf(a2.w, b2.w, acc);
        acc = fmaf(a3.x, b3.x, acc); acc = fmaf(a3.y, b3.y, acc);
        acc = fmaf(a3.z, b3.z, acc); acc = fmaf(a3.w, b3.w, acc);

        // Warp reduce (deterministic tree).
        #pragma unroll
        for (int off = 16; off > 0; off >>= 1)
            acc += __shfl_xor_sync(0xffffffffu, acc, off);

        const float lab = is_pos ? 1.0f : 0.0f;
        term = fmaxf(acc, 0.0f) - acc * lab + log1pf(expf(-fabsf(acc)));
    }

    __shared__ float smem[BLOCK / 32];
    if (lane == 0) smem[wid] = term;
    __syncthreads();
    if (threadIdx.x == 0) {
        float sum = 0.0f;
        #pragma unroll
        for (int i = 0; i < BLOCK / 32; i++) sum += smem[i];
        g_partials[blockIdx.x] = sum;
    }
}

// Kernel 2: single-block reduce, but vectorized + multi-accumulator.
// 25000 partials = 6250 float4; 1024 threads x ~6 float4 each, 4 independent
// accumulator chains -> loads fully pipelined. Fixed order -> deterministic.
__global__ void __launch_bounds__(1024) final_reduce_kernel(
    int n_partials, float inv_total, float* __restrict__ out)
{
    __shared__ float sm[1024];
    const int n4 = n_partials >> 2;   // number of whole float4
    const float4* p4 = reinterpret_cast<const float4*>(g_partials);

    float a0 = 0.0f, a1 = 0.0f, a2 = 0.0f, a3 = 0.0f;
    int i = threadIdx.x;
    for (; i + 3 * 1024 < n4; i += 4 * 1024) {
        float4 v0 = ldcg4(&p4[i + 0 * 1024]);
        float4 v1 = ldcg4(&p4[i + 1 * 1024]);
        float4 v2 = ldcg4(&p4[i + 2 * 1024]);
        float4 v3 = ldcg4(&p4[i + 3 * 1024]);
        a0 += (v0.x + v0.y) + (v0.z + v0.w);
        a1 += (v1.x + v1.y) + (v1.z + v1.w);
        a2 += (v2.x + v2.y) + (v2.z + v2.w);
        a3 += (v3.x + v3.y) + (v3.z + v3.w);
    }
    for (; i < n4; i += 1024) {
        float4 v = ldcg4(&p4[i]);
        a0 += (v.x + v.y) + (v.z + v.w);
    }
    // scalar remainder (n_partials % 4)
    if (threadIdx.x < (n_partials & 3))
        a1 += g_partials[(n4 << 2) + threadIdx.x];

    sm[threadIdx.x] = (a0 + a1) + (a2 + a3);
    __syncthreads();
    #pragma unroll
    for (int s = 512; s > 0; s >>= 1) {
        if (threadIdx.x < s) sm[threadIdx.x] += sm[threadIdx.x + s];
        __syncthreads();
    }
    if (threadIdx.x == 0) *out = sm[0] * inv_total;
}

extern "C" void kernel_launch(void* const* d_in, const int* in_sizes, int n_in,
                              void* d_out, int out_size)
{
    const float* feat    = (const float*)d_in[0];
    const int*   pos_src = (const int*)d_in[1];
    const int*   pos_dst = (const int*)d_in[2];
    const int*   neg_src = (const int*)d_in[3];
    const int*   neg_dst = (const int*)d_in[4];
    float* out = (float*)d_out;

    const int e_pos   = in_sizes[1];
    const int e_neg   = in_sizes[3];
    const int e_total = e_pos + e_neg;

    const int warps_per_block = BLOCK / 32;
    int n_blocks = (e_total + warps_per_block - 1) / warps_per_block;
    if (n_blocks > MAX_BLOCKS) n_blocks = MAX_BLOCKS;  // 200k edges -> 25000

    edge_loss_kernel<<<n_blocks, BLOCK>>>(feat, pos_src, pos_dst,
                                          neg_src, neg_dst, e_pos, e_total);
    final_reduce_kernel<<<1, 1024>>>(n_blocks, 1.0f / (float)e_total, out);
}